// round 3
// baseline (speedup 1.0000x reference)
#include <cuda_runtime.h>
#include <cstdint>

#define DIN  256
#define DOUT 128
#define NP_MAX 100000
#define E_MAX  1600000
#define SLOPE 0.2f

// ---------------- scratch (static device globals; no allocation) ----------------
// Wh order: 0=Wh_P, 1=Wh_A, 2=Wh_p2p, 3=Wh_p2a, 4=Wh_a2p, 5=Wh_a2a
__device__ float g_Wh[6][(size_t)NP_MAX * DOUT];
__device__ float g_ssrc[4][NP_MAX];   // type order: p2p, p2a, a2p, a2a
__device__ float g_sdst[4][NP_MAX];
__device__ float g_m[4][NP_MAX];
__device__ float g_denom[4][NP_MAX];
__device__ float g_ex[4][E_MAX];

// ---------------- GEMM: C[M,128] = A[M,256] @ W[256,128] + b ----------------
// Fuses up to two attention-dot epilogues: s{1,2}[row] = C[row,:] . av{1,2}[0:128].
// TM=64 rows/block, 256 threads. Warp w owns rows w*8..w*8+7; lane owns cols
// lane*4..lane*4+3 (a warp spans the full 128-wide row -> shfl reduce for dots).
__global__ __launch_bounds__(256) void gemm_kernel(
    const float* __restrict__ A, const float* __restrict__ W,
    const float* __restrict__ bias, float* __restrict__ C, int M,
    const float* __restrict__ av1, float* __restrict__ s1,
    const float* __restrict__ av2, float* __restrict__ s2)
{
    __shared__ float As[64][32];
    __shared__ float Bs[32][DOUT];
    const int tid  = threadIdx.x;
    const int lane = tid & 31;
    const int wid  = tid >> 5;
    const int row0 = blockIdx.x * 64;

    float acc[8][4];
#pragma unroll
    for (int r = 0; r < 8; r++)
#pragma unroll
        for (int j = 0; j < 4; j++) acc[r][j] = 0.f;

    for (int k0 = 0; k0 < DIN; k0 += 32) {
        // load A tile (64x32): 512 float4s, 2 per thread
#pragma unroll
        for (int i = 0; i < 2; i++) {
            int idx = tid + i * 256;          // 0..511
            int r = idx >> 3, c4 = idx & 7;   // r in 0..63, c4 in 0..7
            int gr = row0 + r;
            float4 v = make_float4(0.f, 0.f, 0.f, 0.f);
            if (gr < M) v = *(const float4*)(A + (size_t)gr * DIN + k0 + c4 * 4);
            *(float4*)&As[r][c4 * 4] = v;
        }
        // load W tile (32x128): 1024 float4s, 4 per thread
#pragma unroll
        for (int i = 0; i < 4; i++) {
            int idx = tid + i * 256;
            int r = idx >> 5, c4 = idx & 31;  // r in 0..31, c4 in 0..31
            *(float4*)&Bs[r][c4 * 4] =
                *(const float4*)(W + (size_t)(k0 + r) * DOUT + c4 * 4);
        }
        __syncthreads();
#pragma unroll
        for (int kk = 0; kk < 32; kk++) {
            float4 b = *(float4*)&Bs[kk][lane * 4];
#pragma unroll
            for (int r = 0; r < 8; r++) {
                float a = As[wid * 8 + r][kk];   // warp-broadcast LDS
                acc[r][0] += a * b.x;
                acc[r][1] += a * b.y;
                acc[r][2] += a * b.z;
                acc[r][3] += a * b.w;
            }
        }
        __syncthreads();
    }

    float4 bv = *(const float4*)(bias + lane * 4);
    float4 a1v = make_float4(0.f, 0.f, 0.f, 0.f);
    float4 a2v = make_float4(0.f, 0.f, 0.f, 0.f);
    if (av1) a1v = *(const float4*)(av1 + lane * 4);
    if (av2) a2v = *(const float4*)(av2 + lane * 4);

#pragma unroll
    for (int r = 0; r < 8; r++) {
        int row = row0 + wid * 8 + r;   // warp-uniform
        if (row >= M) break;
        float c0 = acc[r][0] + bv.x;
        float c1 = acc[r][1] + bv.y;
        float c2 = acc[r][2] + bv.z;
        float c3 = acc[r][3] + bv.w;
        *(float4*)(C + (size_t)row * DOUT + lane * 4) = make_float4(c0, c1, c2, c3);
        if (av1) {
            float p = c0 * a1v.x + c1 * a1v.y + c2 * a1v.z + c3 * a1v.w;
#pragma unroll
            for (int off = 16; off; off >>= 1) p += __shfl_xor_sync(0xffffffffu, p, off);
            if (lane == 0) s1[row] = p;
        }
        if (av2) {
            float p = c0 * a2v.x + c1 * a2v.y + c2 * a2v.z + c3 * a2v.w;
#pragma unroll
            for (int off = 16; off; off >>= 1) p += __shfl_xor_sync(0xffffffffu, p, off);
            if (lane == 0) s2[row] = p;
        }
    }
}

// ---------------- edge pass 1: segment max (atomic float max trick) ----------------
__global__ __launch_bounds__(256) void edge_max_kernel(
    const int* __restrict__ src, const int* __restrict__ dst,
    const float* __restrict__ ssrc, const float* __restrict__ sdst,
    float* __restrict__ m, int E)
{
    int i = blockIdx.x * blockDim.x + threadIdx.x;
    if (i >= E) return;
    int d = dst[i];
    float e = ssrc[src[i]] + sdst[d];
    e = e > 0.f ? e : SLOPE * e;
    if (e >= 0.f) atomicMax((int*)&m[d], __float_as_int(e));
    else          atomicMin((unsigned int*)&m[d], __float_as_uint(e));
}

// ---------------- edge pass 2: ex = exp(e - m[dst]); denom[dst] += ex ----------------
__global__ __launch_bounds__(256) void edge_exp_kernel(
    const int* __restrict__ src, const int* __restrict__ dst,
    const float* __restrict__ ssrc, const float* __restrict__ sdst,
    const float* __restrict__ m, float* __restrict__ denom,
    float* __restrict__ ex, int E)
{
    int i = blockIdx.x * blockDim.x + threadIdx.x;
    if (i >= E) return;
    int d = dst[i];
    float e = ssrc[src[i]] + sdst[d];
    e = e > 0.f ? e : SLOPE * e;
    float v = __expf(e - m[d]);
    ex[i] = v;
    atomicAdd(&denom[d], v);
}

// ---------------- edge pass 3: recv[dst] += (ex/denom[dst]) * Wh_msg[src] ----------------
// One warp per edge; lane handles 4 features -> 16B vector red.
__global__ __launch_bounds__(256) void edge_scatter_kernel(
    const int* __restrict__ src, const int* __restrict__ dst,
    const float* __restrict__ ex, const float* __restrict__ denom,
    const float* __restrict__ Wh_msg, float* __restrict__ recv, int E)
{
    int gw   = (blockIdx.x * blockDim.x + threadIdx.x) >> 5;
    int lane = threadIdx.x & 31;
    if (gw >= E) return;
    int s = src[gw], d = dst[gw];
    float alpha = ex[gw] / denom[d];
    float4 v = *(const float4*)(Wh_msg + (size_t)s * DOUT + lane * 4);
    v.x *= alpha; v.y *= alpha; v.z *= alpha; v.w *= alpha;
    float* p = recv + (size_t)d * DOUT + lane * 4;
    asm volatile("red.global.add.v4.f32 [%0], {%1,%2,%3,%4};"
                 :: "l"(p), "f"(v.x), "f"(v.y), "f"(v.z), "f"(v.w) : "memory");
}

// ---------------- finalize: out = relu(Wh + out) ----------------
__global__ __launch_bounds__(256) void finalize_kernel(
    const float* __restrict__ Wh, float* __restrict__ out, int n4)
{
    int i = blockIdx.x * blockDim.x + threadIdx.x;
    if (i >= n4) return;
    float4 w = ((const float4*)Wh)[i];
    float4 o = ((float4*)out)[i];
    float4 r;
    r.x = fmaxf(w.x + o.x, 0.f);
    r.y = fmaxf(w.y + o.y, 0.f);
    r.z = fmaxf(w.z + o.z, 0.f);
    r.w = fmaxf(w.w + o.w, 0.f);
    ((float4*)out)[i] = r;
}

// ---------------- host launcher ----------------
extern "C" void kernel_launch(void* const* d_in, const int* in_sizes, int n_in,
                              void* d_out, int out_size)
{
    (void)n_in;
    const float* feat_P = (const float*)d_in[0];
    const float* feat_A = (const float*)d_in[1];
    const int* e_src[4] = { (const int*)d_in[2], (const int*)d_in[4],
                            (const int*)d_in[6], (const int*)d_in[8] };  // p2p,p2a,a2p,a2a
    const int* e_dst[4] = { (const int*)d_in[3], (const int*)d_in[5],
                            (const int*)d_in[7], (const int*)d_in[9] };
    const int  e_cnt[4] = { in_sizes[2], in_sizes[4], in_sizes[6], in_sizes[8] };

    const float* W_P   = (const float*)d_in[10]; const float* b_P   = (const float*)d_in[11];
    const float* W_A   = (const float*)d_in[12]; const float* b_A   = (const float*)d_in[13];
    const float* W_p2p = (const float*)d_in[14]; const float* b_p2p = (const float*)d_in[15];
    const float* W_p2a = (const float*)d_in[16]; const float* b_p2a = (const float*)d_in[17];
    const float* W_a2p = (const float*)d_in[18]; const float* b_a2p = (const float*)d_in[19];
    const float* W_a2a = (const float*)d_in[20]; const float* b_a2a = (const float*)d_in[21];
    const float* a_p2p = (const float*)d_in[22];
    const float* a_p2a = (const float*)d_in[23];
    const float* a_a2p = (const float*)d_in[24];
    const float* a_a2a = (const float*)d_in[25];

    const int n_p = in_sizes[0] / DIN;
    const int n_a = in_sizes[1] / DIN;

    float *whb, *ssrcb, *sdstb, *mb, *denomb, *exb;
    cudaGetSymbolAddress((void**)&whb,    g_Wh);
    cudaGetSymbolAddress((void**)&ssrcb,  g_ssrc);
    cudaGetSymbolAddress((void**)&sdstb,  g_sdst);
    cudaGetSymbolAddress((void**)&mb,     g_m);
    cudaGetSymbolAddress((void**)&denomb, g_denom);
    cudaGetSymbolAddress((void**)&exb,    g_ex);

    float* Wh[6];
    for (int i = 0; i < 6; i++) Wh[i] = whb + (size_t)i * NP_MAX * DOUT;

    float* outP = (float*)d_out;
    float* outA = outP + (size_t)n_p * DOUT;

    // init accumulators
    cudaMemsetAsync(d_out, 0, (size_t)out_size * sizeof(float));
    cudaMemsetAsync(mb, 0xFF, 4 * (size_t)NP_MAX * sizeof(float));  // -NaN bits: works with int/uint atomic trick
    cudaMemsetAsync(denomb, 0, 4 * (size_t)NP_MAX * sizeof(float));

    // 6 projections (+ fused attention dots)
    int gP = (n_p + 63) / 64, gA = (n_a + 63) / 64;
    gemm_kernel<<<gP, 256>>>(feat_P, W_P,   b_P,   Wh[0], n_p,
                             a_p2p + DOUT, sdstb + 0 * NP_MAX,
                             a_a2p + DOUT, sdstb + 2 * NP_MAX);
    gemm_kernel<<<gA, 256>>>(feat_A, W_A,   b_A,   Wh[1], n_a,
                             a_p2a + DOUT, sdstb + 1 * NP_MAX,
                             a_a2a + DOUT, sdstb + 3 * NP_MAX);
    gemm_kernel<<<gP, 256>>>(feat_P, W_p2p, b_p2p, Wh[2], n_p,
                             a_p2p, ssrcb + 0 * NP_MAX, nullptr, nullptr);
    gemm_kernel<<<gP, 256>>>(feat_P, W_p2a, b_p2a, Wh[3], n_p,
                             a_p2a, ssrcb + 1 * NP_MAX, nullptr, nullptr);
    gemm_kernel<<<gA, 256>>>(feat_A, W_a2p, b_a2p, Wh[4], n_a,
                             a_a2p, ssrcb + 2 * NP_MAX, nullptr, nullptr);
    gemm_kernel<<<gA, 256>>>(feat_A, W_a2a, b_a2a, Wh[5], n_a,
                             a_a2a, ssrcb + 3 * NP_MAX, nullptr, nullptr);

    // per edge type: msg Wh index and recv target
    const int   msg_idx[4]  = { 2, 3, 4, 5 };         // p2p, p2a, a2p, a2a messages
    float*      recv_tgt[4] = { outP, outA, outP, outA };

    for (int t = 0; t < 4; t++) {
        int E = e_cnt[t];
        int gb = (E + 255) / 256;
        edge_max_kernel<<<gb, 256>>>(e_src[t], e_dst[t],
                                     ssrcb + (size_t)t * NP_MAX, sdstb + (size_t)t * NP_MAX,
                                     mb + (size_t)t * NP_MAX, E);
        edge_exp_kernel<<<gb, 256>>>(e_src[t], e_dst[t],
                                     ssrcb + (size_t)t * NP_MAX, sdstb + (size_t)t * NP_MAX,
                                     mb + (size_t)t * NP_MAX, denomb + (size_t)t * NP_MAX,
                                     exb + (size_t)t * E_MAX, E);
        int gs = (E + 7) / 8;  // one warp per edge, 8 warps/block
        edge_scatter_kernel<<<gs, 256>>>(e_src[t], e_dst[t],
                                         exb + (size_t)t * E_MAX, denomb + (size_t)t * NP_MAX,
                                         Wh[msg_idx[t]], recv_tgt[t], E);
    }

    // h = relu(Wh + recv)
    int n4P = n_p * DOUT / 4, n4A = n_a * DOUT / 4;
    finalize_kernel<<<(n4P + 255) / 256, 256>>>(Wh[0], outP, n4P);
    finalize_kernel<<<(n4A + 255) / 256, 256>>>(Wh[1], outA, n4A);
}

// round 4
// speedup vs baseline: 1.4648x; 1.4648x over previous
#include <cuda_runtime.h>
#include <cstdint>

#define DIN  256
#define DOUT 128
#define NP_MAX 100000
#define E_MAX  1600000
#define SLOPE 0.2f

// ---------------- scratch (static device globals; no allocation) ----------------
// Wh order: 0=Wh_P, 1=Wh_A, 2=Wh_p2p, 3=Wh_p2a, 4=Wh_a2p, 5=Wh_a2a
__device__ float g_Wh[6][(size_t)NP_MAX * DOUT];
__device__ float g_ssrc[4][NP_MAX];   // type order: p2p, p2a, a2p, a2a
__device__ float g_sdst[4][NP_MAX];
__device__ float g_m[4][NP_MAX];
__device__ float g_denom[4][NP_MAX];
__device__ float g_ex[4][E_MAX];

// ================= TF32 tensor-core GEMM =================
// C_g[M,128] = A[M,256] @ W_g[256,128] + b_g   for g = blockIdx.x in {0,1,2}
// Block tile 128x128, BK=32, 8 warps, warp tile 64x32 (warp grid 2x4).
// Fused epilogue: up to two per-row dot products with 128-vectors (attention scores).

#define ASTRIDE 36   // 128 x 36 floats per A buffer (conflict-free: 36%32==4)
#define BSTRIDE 136  // 32 x 136 floats per B buffer (conflict-free: 136%32==8)
#define ASZ (128 * ASTRIDE)
#define BSZ (32 * BSTRIDE)
#define SMEM_DYN ((2 * ASZ + 2 * BSZ) * 4)

struct GemmArgs {
    const float* A; int M;
    const float* W[3];
    const float* bias[3];
    float* C[3];
    const float* av0[3]; float* s0[3];
    const float* av1[3]; float* s1[3];
};

__device__ __forceinline__ void cp_async16(void* smem_dst, const void* gsrc, bool pred) {
    uint32_t addr = (uint32_t)__cvta_generic_to_shared(smem_dst);
    int sz = pred ? 16 : 0;
    asm volatile("cp.async.cg.shared.global [%0], [%1], 16, %2;\n"
                 :: "r"(addr), "l"(gsrc), "r"(sz) : "memory");
}
__device__ __forceinline__ void cp_commit() {
    asm volatile("cp.async.commit_group;\n" ::: "memory");
}
__device__ __forceinline__ uint32_t f2tf32(float f) {
    uint32_t u;
    asm("cvt.rna.tf32.f32 %0, %1;" : "=r"(u) : "f"(f));
    return u;
}
__device__ __forceinline__ void mma_tf32(float c[4], const uint32_t a[4], uint32_t b0, uint32_t b1) {
    asm volatile(
        "mma.sync.aligned.m16n8k8.row.col.f32.tf32.tf32.f32 "
        "{%0,%1,%2,%3}, {%4,%5,%6,%7}, {%8,%9}, {%0,%1,%2,%3};"
        : "+f"(c[0]), "+f"(c[1]), "+f"(c[2]), "+f"(c[3])
        : "r"(a[0]), "r"(a[1]), "r"(a[2]), "r"(a[3]), "r"(b0), "r"(b1));
}

__global__ __launch_bounds__(256, 2) void gemm_tc_kernel(GemmArgs ga) {
    extern __shared__ float sm[];
    float* As = sm;               // 2 buffers of ASZ
    float* Bs = sm + 2 * ASZ;     // 2 buffers of BSZ

    const int g    = blockIdx.x;
    const int row0 = blockIdx.y * 128;
    const int tid  = threadIdx.x;
    const int lane = tid & 31;
    const int wid  = tid >> 5;
    const int wm   = wid & 1;     // 0..1  (64-row halves)
    const int wn   = wid >> 1;    // 0..3  (32-col quarters)
    const int M    = ga.M;
    const float* A = ga.A;
    const float* W = ga.W[g];

    float c[4][4][4];
#pragma unroll
    for (int mf = 0; mf < 4; mf++)
#pragma unroll
        for (int nf = 0; nf < 4; nf++)
#pragma unroll
            for (int j = 0; j < 4; j++) c[mf][nf][j] = 0.f;

    // ---- tile loaders (cp.async) ----
    auto loadA = [&](int k0, int buf) {
        float* dst = As + buf * ASZ;
#pragma unroll
        for (int i = 0; i < 4; i++) {
            int idx = tid + i * 256;            // 0..1023
            int r = idx >> 3, c4 = idx & 7;     // r:0..127, c4:0..7
            int gr = row0 + r;
            int grc = gr < M ? gr : (M - 1);
            cp_async16(dst + r * ASTRIDE + c4 * 4,
                       A + (size_t)grc * DIN + k0 + c4 * 4, gr < M);
        }
    };
    auto loadB = [&](int k0, int buf) {
        float* dst = Bs + buf * BSZ;
#pragma unroll
        for (int i = 0; i < 4; i++) {
            int idx = tid + i * 256;            // 0..1023
            int kr = idx >> 5, c4 = idx & 31;   // kr:0..31, c4:0..31
            cp_async16(dst + kr * BSTRIDE + c4 * 4,
                       W + (size_t)(k0 + kr) * DOUT + c4 * 4, true);
        }
    };

    loadA(0, 0); loadB(0, 0); cp_commit();

    const int lq = lane >> 2;   // 0..7
    const int lr = lane & 3;    // 0..3

#pragma unroll 1
    for (int ch = 0; ch < 8; ch++) {
        if (ch < 7) {
            loadA((ch + 1) * 32, (ch + 1) & 1);
            loadB((ch + 1) * 32, (ch + 1) & 1);
            cp_commit();
            asm volatile("cp.async.wait_group 1;\n" ::: "memory");
        } else {
            asm volatile("cp.async.wait_group 0;\n" ::: "memory");
        }
        __syncthreads();

        const float* Ab = As + (ch & 1) * ASZ;
        const float* Bb = Bs + (ch & 1) * BSZ;

#pragma unroll
        for (int kk = 0; kk < 4; kk++) {
            uint32_t a[4][4];
#pragma unroll
            for (int mf = 0; mf < 4; mf++) {
                int r0 = wm * 64 + mf * 16 + lq;
                int k  = kk * 8 + lr;
                a[mf][0] = f2tf32(Ab[r0 * ASTRIDE + k]);
                a[mf][1] = f2tf32(Ab[(r0 + 8) * ASTRIDE + k]);
                a[mf][2] = f2tf32(Ab[r0 * ASTRIDE + k + 4]);
                a[mf][3] = f2tf32(Ab[(r0 + 8) * ASTRIDE + k + 4]);
            }
#pragma unroll
            for (int nf = 0; nf < 4; nf++) {
                int col = wn * 32 + nf * 8 + lq;
                int k   = kk * 8 + lr;
                uint32_t b0 = f2tf32(Bb[k * BSTRIDE + col]);
                uint32_t b1 = f2tf32(Bb[(k + 4) * BSTRIDE + col]);
#pragma unroll
                for (int mf = 0; mf < 4; mf++)
                    mma_tf32(c[mf][nf], a[mf], b0, b1);
            }
        }
        __syncthreads();
    }

    // ---- epilogue: bias add, store C, fused row-dot(s) ----
    float* sdot = sm;             // reuse As buffer 0: 256 floats
    sdot[tid] = 0.f;
    __syncthreads();

    const float* bias = ga.bias[g];
    float* C = ga.C[g];
    const float* avA = ga.av0[g]; float* sA = ga.s0[g];
    const float* avB = ga.av1[g]; float* sB = ga.s1[g];

    float2 bv[4], aAv[4], aBv[4];
#pragma unroll
    for (int nf = 0; nf < 4; nf++) {
        int col = wn * 32 + nf * 8 + 2 * lr;
        bv[nf] = *(const float2*)(bias + col);
        aAv[nf] = make_float2(0.f, 0.f);
        aBv[nf] = make_float2(0.f, 0.f);
        if (avA) aAv[nf] = *(const float2*)(avA + col);
        if (avB) aBv[nf] = *(const float2*)(avB + col);
    }

#pragma unroll
    for (int mf = 0; mf < 4; mf++) {
        int rl_lo = wm * 64 + mf * 16 + lq;     // local row 0..127
        int rl_hi = rl_lo + 8;
        int rlo = row0 + rl_lo, rhi = row0 + rl_hi;
        float pAlo = 0.f, pAhi = 0.f, pBlo = 0.f, pBhi = 0.f;
#pragma unroll
        for (int nf = 0; nf < 4; nf++) {
            int col = wn * 32 + nf * 8 + 2 * lr;
            float v0 = c[mf][nf][0] + bv[nf].x;
            float v1 = c[mf][nf][1] + bv[nf].y;
            float v2 = c[mf][nf][2] + bv[nf].x;
            float v3 = c[mf][nf][3] + bv[nf].y;
            if (rlo < M) *(float2*)(C + (size_t)rlo * DOUT + col) = make_float2(v0, v1);
            if (rhi < M) *(float2*)(C + (size_t)rhi * DOUT + col) = make_float2(v2, v3);
            pAlo += v0 * aAv[nf].x + v1 * aAv[nf].y;
            pAhi += v2 * aAv[nf].x + v3 * aAv[nf].y;
            pBlo += v0 * aBv[nf].x + v1 * aBv[nf].y;
            pBhi += v2 * aBv[nf].x + v3 * aBv[nf].y;
        }
        // reduce within quad (lanes sharing the same row)
#pragma unroll
        for (int off = 1; off <= 2; off <<= 1) {
            pAlo += __shfl_xor_sync(0xffffffffu, pAlo, off);
            pAhi += __shfl_xor_sync(0xffffffffu, pAhi, off);
            pBlo += __shfl_xor_sync(0xffffffffu, pBlo, off);
            pBhi += __shfl_xor_sync(0xffffffffu, pBhi, off);
        }
        if (lr == 0) {
            if (avA) { atomicAdd(&sdot[rl_lo], pAlo); atomicAdd(&sdot[rl_hi], pAhi); }
            if (avB) { atomicAdd(&sdot[128 + rl_lo], pBlo); atomicAdd(&sdot[128 + rl_hi], pBhi); }
        }
    }
    __syncthreads();
    if (tid < 128) {
        int row = row0 + tid;
        if (row < M) {
            if (sA) sA[row] = sdot[tid];
            if (sB) sB[row] = sdot[128 + tid];
        }
    }
}

// ---------------- edge pass 1: segment max (atomic float max trick) ----------------
__global__ __launch_bounds__(256) void edge_max_kernel(
    const int* __restrict__ src, const int* __restrict__ dst,
    const float* __restrict__ ssrc, const float* __restrict__ sdst,
    float* __restrict__ m, int E)
{
    int i = blockIdx.x * blockDim.x + threadIdx.x;
    if (i >= E) return;
    int d = dst[i];
    float e = ssrc[src[i]] + sdst[d];
    e = e > 0.f ? e : SLOPE * e;
    if (e >= 0.f) atomicMax((int*)&m[d], __float_as_int(e));
    else          atomicMin((unsigned int*)&m[d], __float_as_uint(e));
}

// ---------------- edge pass 2: ex = exp(e - m[dst]); denom[dst] += ex ----------------
__global__ __launch_bounds__(256) void edge_exp_kernel(
    const int* __restrict__ src, const int* __restrict__ dst,
    const float* __restrict__ ssrc, const float* __restrict__ sdst,
    const float* __restrict__ m, float* __restrict__ denom,
    float* __restrict__ ex, int E)
{
    int i = blockIdx.x * blockDim.x + threadIdx.x;
    if (i >= E) return;
    int d = dst[i];
    float e = ssrc[src[i]] + sdst[d];
    e = e > 0.f ? e : SLOPE * e;
    float v = __expf(e - m[d]);
    ex[i] = v;
    atomicAdd(&denom[d], v);
}

// ---------------- edge pass 3: recv[dst] += (ex/denom[dst]) * Wh_msg[src] ----------------
__global__ __launch_bounds__(256) void edge_scatter_kernel(
    const int* __restrict__ src, const int* __restrict__ dst,
    const float* __restrict__ ex, const float* __restrict__ denom,
    const float* __restrict__ Wh_msg, float* __restrict__ recv, int E)
{
    int gw   = (blockIdx.x * blockDim.x + threadIdx.x) >> 5;
    int lane = threadIdx.x & 31;
    if (gw >= E) return;
    int s = src[gw], d = dst[gw];
    float alpha = ex[gw] / denom[d];
    float4 v = *(const float4*)(Wh_msg + (size_t)s * DOUT + lane * 4);
    v.x *= alpha; v.y *= alpha; v.z *= alpha; v.w *= alpha;
    float* p = recv + (size_t)d * DOUT + lane * 4;
    asm volatile("red.global.add.v4.f32 [%0], {%1,%2,%3,%4};"
                 :: "l"(p), "f"(v.x), "f"(v.y), "f"(v.z), "f"(v.w) : "memory");
}

// ---------------- finalize: out = relu(Wh + out) ----------------
__global__ __launch_bounds__(256) void finalize_kernel(
    const float* __restrict__ Wh, float* __restrict__ out, int n4)
{
    int i = blockIdx.x * blockDim.x + threadIdx.x;
    if (i >= n4) return;
    float4 w = ((const float4*)Wh)[i];
    float4 o = ((float4*)out)[i];
    float4 r;
    r.x = fmaxf(w.x + o.x, 0.f);
    r.y = fmaxf(w.y + o.y, 0.f);
    r.z = fmaxf(w.z + o.z, 0.f);
    r.w = fmaxf(w.w + o.w, 0.f);
    ((float4*)out)[i] = r;
}

// ---------------- host launcher ----------------
extern "C" void kernel_launch(void* const* d_in, const int* in_sizes, int n_in,
                              void* d_out, int out_size)
{
    (void)n_in;
    const float* feat_P = (const float*)d_in[0];
    const float* feat_A = (const float*)d_in[1];
    const int* e_src[4] = { (const int*)d_in[2], (const int*)d_in[4],
                            (const int*)d_in[6], (const int*)d_in[8] };  // p2p,p2a,a2p,a2a
    const int* e_dst[4] = { (const int*)d_in[3], (const int*)d_in[5],
                            (const int*)d_in[7], (const int*)d_in[9] };
    const int  e_cnt[4] = { in_sizes[2], in_sizes[4], in_sizes[6], in_sizes[8] };

    const float* W_P   = (const float*)d_in[10]; const float* b_P   = (const float*)d_in[11];
    const float* W_A   = (const float*)d_in[12]; const float* b_A   = (const float*)d_in[13];
    const float* W_p2p = (const float*)d_in[14]; const float* b_p2p = (const float*)d_in[15];
    const float* W_p2a = (const float*)d_in[16]; const float* b_p2a = (const float*)d_in[17];
    const float* W_a2p = (const float*)d_in[18]; const float* b_a2p = (const float*)d_in[19];
    const float* W_a2a = (const float*)d_in[20]; const float* b_a2a = (const float*)d_in[21];
    const float* a_p2p = (const float*)d_in[22];
    const float* a_p2a = (const float*)d_in[23];
    const float* a_a2p = (const float*)d_in[24];
    const float* a_a2a = (const float*)d_in[25];

    const int n_p = in_sizes[0] / DIN;
    const int n_a = in_sizes[1] / DIN;

    float *whb, *ssrcb, *sdstb, *mb, *denomb, *exb;
    cudaGetSymbolAddress((void**)&whb,    g_Wh);
    cudaGetSymbolAddress((void**)&ssrcb,  g_ssrc);
    cudaGetSymbolAddress((void**)&sdstb,  g_sdst);
    cudaGetSymbolAddress((void**)&mb,     g_m);
    cudaGetSymbolAddress((void**)&denomb, g_denom);
    cudaGetSymbolAddress((void**)&exb,    g_ex);

    float* Wh[6];
    for (int i = 0; i < 6; i++) Wh[i] = whb + (size_t)i * NP_MAX * DOUT;

    float* outP = (float*)d_out;
    float* outA = outP + (size_t)n_p * DOUT;

    // init accumulators
    cudaMemsetAsync(d_out, 0, (size_t)out_size * sizeof(float));
    cudaMemsetAsync(mb, 0xFF, 4 * (size_t)NP_MAX * sizeof(float));  // -NaN bits for atomic max trick
    cudaMemsetAsync(denomb, 0, 4 * (size_t)NP_MAX * sizeof(float));

    // tensor-core GEMMs: one launch per node type, 3 weight groups each
    cudaFuncSetAttribute(gemm_tc_kernel, cudaFuncAttributeMaxDynamicSharedMemorySize, SMEM_DYN);

    GemmArgs gp;
    gp.A = feat_P; gp.M = n_p;
    gp.W[0] = W_P;   gp.bias[0] = b_P;   gp.C[0] = Wh[0];
    gp.W[1] = W_p2p; gp.bias[1] = b_p2p; gp.C[1] = Wh[2];
    gp.W[2] = W_p2a; gp.bias[2] = b_p2a; gp.C[2] = Wh[3];
    gp.av0[0] = a_p2p + DOUT; gp.s0[0] = sdstb + 0 * NP_MAX;
    gp.av1[0] = a_a2p + DOUT; gp.s1[0] = sdstb + 2 * NP_MAX;
    gp.av0[1] = a_p2p;        gp.s0[1] = ssrcb + 0 * NP_MAX;
    gp.av1[1] = nullptr;      gp.s1[1] = nullptr;
    gp.av0[2] = a_p2a;        gp.s0[2] = ssrcb + 1 * NP_MAX;
    gp.av1[2] = nullptr;      gp.s1[2] = nullptr;

    GemmArgs gaa;
    gaa.A = feat_A; gaa.M = n_a;
    gaa.W[0] = W_A;   gaa.bias[0] = b_A;   gaa.C[0] = Wh[1];
    gaa.W[1] = W_a2p; gaa.bias[1] = b_a2p; gaa.C[1] = Wh[4];
    gaa.W[2] = W_a2a; gaa.bias[2] = b_a2a; gaa.C[2] = Wh[5];
    gaa.av0[0] = a_p2a + DOUT; gaa.s0[0] = sdstb + 1 * NP_MAX;
    gaa.av1[0] = a_a2a + DOUT; gaa.s1[0] = sdstb + 3 * NP_MAX;
    gaa.av0[1] = a_a2p;        gaa.s0[1] = ssrcb + 2 * NP_MAX;
    gaa.av1[1] = nullptr;      gaa.s1[1] = nullptr;
    gaa.av0[2] = a_a2a;        gaa.s0[2] = ssrcb + 3 * NP_MAX;
    gaa.av1[2] = nullptr;      gaa.s1[2] = nullptr;

    gemm_tc_kernel<<<dim3(3, (n_p + 127) / 128), 256, SMEM_DYN>>>(gp);
    gemm_tc_kernel<<<dim3(3, (n_a + 127) / 128), 256, SMEM_DYN>>>(gaa);

    // per edge type: msg Wh index and recv target
    const int   msg_idx[4]  = { 2, 3, 4, 5 };         // p2p, p2a, a2p, a2a messages
    float*      recv_tgt[4] = { outP, outA, outP, outA };

    for (int t = 0; t < 4; t++) {
        int E = e_cnt[t];
        int gb = (E + 255) / 256;
        edge_max_kernel<<<gb, 256>>>(e_src[t], e_dst[t],
                                     ssrcb + (size_t)t * NP_MAX, sdstb + (size_t)t * NP_MAX,
                                     mb + (size_t)t * NP_MAX, E);
        edge_exp_kernel<<<gb, 256>>>(e_src[t], e_dst[t],
                                     ssrcb + (size_t)t * NP_MAX, sdstb + (size_t)t * NP_MAX,
                                     mb + (size_t)t * NP_MAX, denomb + (size_t)t * NP_MAX,
                                     exb + (size_t)t * E_MAX, E);
        int gs = (E + 7) / 8;  // one warp per edge, 8 warps/block
        edge_scatter_kernel<<<gs, 256>>>(e_src[t], e_dst[t],
                                         exb + (size_t)t * E_MAX, denomb + (size_t)t * NP_MAX,
                                         Wh[msg_idx[t]], recv_tgt[t], E);
    }

    // h = relu(Wh + recv)
    int n4P = n_p * DOUT / 4, n4A = n_a * DOUT / 4;
    finalize_kernel<<<(n4P + 255) / 256, 256>>>(Wh[0], outP, n4P);
    finalize_kernel<<<(n4A + 255) / 256, 256>>>(Wh[1], outA, n4A);
}

// round 7
// speedup vs baseline: 2.7599x; 1.8842x over previous
#include <cuda_runtime.h>
#include <cstdint>

#define DIN  256
#define DOUT 128
#define NP_MAX 100000
#define E_MAX  1600000
#define SLOPE 0.2f

// ---------------- scratch (static device globals; no allocation) ----------------
// Wh order: 0=Wh_P, 1=Wh_A, 2=Wh_p2p, 3=Wh_p2a, 4=Wh_a2p, 5=Wh_a2a
__device__ float g_Wh[6][(size_t)NP_MAX * DOUT];
__device__ float g_ssrc[4][NP_MAX];   // type order: p2p, p2a, a2p, a2a
__device__ float g_sdst[4][NP_MAX];
__device__ int   g_cnt[4][NP_MAX];      // per-dst degree (histogram)
__device__ int   g_cur[4][NP_MAX];      // fill cursors
__device__ int   g_off[4][NP_MAX + 1];  // CSR row offsets
__device__ int   g_part[4][512];        // scan block partials
__device__ int   g_srcp[4][E_MAX];      // src ids permuted into CSR order

// ================= TF32 tensor-core GEMM (unchanged from R3) =================
#define ASTRIDE 36
#define BSTRIDE 136
#define ASZ (128 * ASTRIDE)
#define BSZ (32 * BSTRIDE)
#define SMEM_DYN ((2 * ASZ + 2 * BSZ) * 4)

struct GemmArgs {
    const float* A; int M;
    const float* W[3];
    const float* bias[3];
    float* C[3];
    const float* av0[3]; float* s0[3];
    const float* av1[3]; float* s1[3];
};

__device__ __forceinline__ void cp_async16(void* smem_dst, const void* gsrc, bool pred) {
    uint32_t addr = (uint32_t)__cvta_generic_to_shared(smem_dst);
    int sz = pred ? 16 : 0;
    asm volatile("cp.async.cg.shared.global [%0], [%1], 16, %2;\n"
                 :: "r"(addr), "l"(gsrc), "r"(sz) : "memory");
}
__device__ __forceinline__ void cp_commit() {
    asm volatile("cp.async.commit_group;\n" ::: "memory");
}
__device__ __forceinline__ uint32_t f2tf32(float f) {
    uint32_t u;
    asm("cvt.rna.tf32.f32 %0, %1;" : "=r"(u) : "f"(f));
    return u;
}
__device__ __forceinline__ void mma_tf32(float c[4], const uint32_t a[4], uint32_t b0, uint32_t b1) {
    asm volatile(
        "mma.sync.aligned.m16n8k8.row.col.f32.tf32.tf32.f32 "
        "{%0,%1,%2,%3}, {%4,%5,%6,%7}, {%8,%9}, {%0,%1,%2,%3};"
        : "+f"(c[0]), "+f"(c[1]), "+f"(c[2]), "+f"(c[3])
        : "r"(a[0]), "r"(a[1]), "r"(a[2]), "r"(a[3]), "r"(b0), "r"(b1));
}

__global__ __launch_bounds__(256, 2) void gemm_tc_kernel(GemmArgs ga) {
    extern __shared__ float sm[];
    float* As = sm;
    float* Bs = sm + 2 * ASZ;

    const int g    = blockIdx.x;
    const int row0 = blockIdx.y * 128;
    const int tid  = threadIdx.x;
    const int lane = tid & 31;
    const int wid  = tid >> 5;
    const int wm   = wid & 1;
    const int wn   = wid >> 1;
    const int M    = ga.M;
    const float* A = ga.A;
    const float* W = ga.W[g];

    float c[4][4][4];
#pragma unroll
    for (int mf = 0; mf < 4; mf++)
#pragma unroll
        for (int nf = 0; nf < 4; nf++)
#pragma unroll
            for (int j = 0; j < 4; j++) c[mf][nf][j] = 0.f;

    auto loadA = [&](int k0, int buf) {
        float* dst = As + buf * ASZ;
#pragma unroll
        for (int i = 0; i < 4; i++) {
            int idx = tid + i * 256;
            int r = idx >> 3, c4 = idx & 7;
            int gr = row0 + r;
            int grc = gr < M ? gr : (M - 1);
            cp_async16(dst + r * ASTRIDE + c4 * 4,
                       A + (size_t)grc * DIN + k0 + c4 * 4, gr < M);
        }
    };
    auto loadB = [&](int k0, int buf) {
        float* dst = Bs + buf * BSZ;
#pragma unroll
        for (int i = 0; i < 4; i++) {
            int idx = tid + i * 256;
            int kr = idx >> 5, c4 = idx & 31;
            cp_async16(dst + kr * BSTRIDE + c4 * 4,
                       W + (size_t)(k0 + kr) * DOUT + c4 * 4, true);
        }
    };

    loadA(0, 0); loadB(0, 0); cp_commit();

    const int lq = lane >> 2;
    const int lr = lane & 3;

#pragma unroll 1
    for (int ch = 0; ch < 8; ch++) {
        if (ch < 7) {
            loadA((ch + 1) * 32, (ch + 1) & 1);
            loadB((ch + 1) * 32, (ch + 1) & 1);
            cp_commit();
            asm volatile("cp.async.wait_group 1;\n" ::: "memory");
        } else {
            asm volatile("cp.async.wait_group 0;\n" ::: "memory");
        }
        __syncthreads();

        const float* Ab = As + (ch & 1) * ASZ;
        const float* Bb = Bs + (ch & 1) * BSZ;

#pragma unroll
        for (int kk = 0; kk < 4; kk++) {
            uint32_t a[4][4];
#pragma unroll
            for (int mf = 0; mf < 4; mf++) {
                int r0 = wm * 64 + mf * 16 + lq;
                int k  = kk * 8 + lr;
                a[mf][0] = f2tf32(Ab[r0 * ASTRIDE + k]);
                a[mf][1] = f2tf32(Ab[(r0 + 8) * ASTRIDE + k]);
                a[mf][2] = f2tf32(Ab[r0 * ASTRIDE + k + 4]);
                a[mf][3] = f2tf32(Ab[(r0 + 8) * ASTRIDE + k + 4]);
            }
#pragma unroll
            for (int nf = 0; nf < 4; nf++) {
                int col = wn * 32 + nf * 8 + lq;
                int k   = kk * 8 + lr;
                uint32_t b0 = f2tf32(Bb[k * BSTRIDE + col]);
                uint32_t b1 = f2tf32(Bb[(k + 4) * BSTRIDE + col]);
#pragma unroll
                for (int mf = 0; mf < 4; mf++)
                    mma_tf32(c[mf][nf], a[mf], b0, b1);
            }
        }
        __syncthreads();
    }

    float* sdot = sm;
    sdot[tid] = 0.f;
    __syncthreads();

    const float* bias = ga.bias[g];
    float* C = ga.C[g];
    const float* avA = ga.av0[g]; float* sA = ga.s0[g];
    const float* avB = ga.av1[g]; float* sB = ga.s1[g];

    float2 bv[4], aAv[4], aBv[4];
#pragma unroll
    for (int nf = 0; nf < 4; nf++) {
        int col = wn * 32 + nf * 8 + 2 * lr;
        bv[nf] = *(const float2*)(bias + col);
        aAv[nf] = make_float2(0.f, 0.f);
        aBv[nf] = make_float2(0.f, 0.f);
        if (avA) aAv[nf] = *(const float2*)(avA + col);
        if (avB) aBv[nf] = *(const float2*)(avB + col);
    }

#pragma unroll
    for (int mf = 0; mf < 4; mf++) {
        int rl_lo = wm * 64 + mf * 16 + lq;
        int rl_hi = rl_lo + 8;
        int rlo = row0 + rl_lo, rhi = row0 + rl_hi;
        float pAlo = 0.f, pAhi = 0.f, pBlo = 0.f, pBhi = 0.f;
#pragma unroll
        for (int nf = 0; nf < 4; nf++) {
            int col = wn * 32 + nf * 8 + 2 * lr;
            float v0 = c[mf][nf][0] + bv[nf].x;
            float v1 = c[mf][nf][1] + bv[nf].y;
            float v2 = c[mf][nf][2] + bv[nf].x;
            float v3 = c[mf][nf][3] + bv[nf].y;
            if (rlo < M) *(float2*)(C + (size_t)rlo * DOUT + col) = make_float2(v0, v1);
            if (rhi < M) *(float2*)(C + (size_t)rhi * DOUT + col) = make_float2(v2, v3);
            pAlo += v0 * aAv[nf].x + v1 * aAv[nf].y;
            pAhi += v2 * aAv[nf].x + v3 * aAv[nf].y;
            pBlo += v0 * aBv[nf].x + v1 * aBv[nf].y;
            pBhi += v2 * aBv[nf].x + v3 * aBv[nf].y;
        }
#pragma unroll
        for (int off = 1; off <= 2; off <<= 1) {
            pAlo += __shfl_xor_sync(0xffffffffu, pAlo, off);
            pAhi += __shfl_xor_sync(0xffffffffu, pAhi, off);
            pBlo += __shfl_xor_sync(0xffffffffu, pBlo, off);
            pBhi += __shfl_xor_sync(0xffffffffu, pBhi, off);
        }
        if (lr == 0) {
            if (avA) { atomicAdd(&sdot[rl_lo], pAlo); atomicAdd(&sdot[rl_hi], pAhi); }
            if (avB) { atomicAdd(&sdot[128 + rl_lo], pBlo); atomicAdd(&sdot[128 + rl_hi], pBhi); }
        }
    }
    __syncthreads();
    if (tid < 128) {
        int row = row0 + tid;
        if (row < M) {
            if (sA) sA[row] = sdot[tid];
            if (sB) sB[row] = sdot[128 + tid];
        }
    }
}

// ================= CSR build (counting sort by dst) =================
__global__ __launch_bounds__(256) void hist_kernel(
    const int* __restrict__ dst, int* __restrict__ cnt, int E)
{
    int i = blockIdx.x * blockDim.x + threadIdx.x;
    if (i < E) atomicAdd(&cnt[dst[i]], 1);
}

__global__ __launch_bounds__(256) void scan1_kernel(
    const int* __restrict__ cnt, int* __restrict__ part, int n)
{
    __shared__ int s[256];
    int t = threadIdx.x;
    int i = blockIdx.x * 256 + t;
    s[t] = (i < n) ? cnt[i] : 0;
    __syncthreads();
#pragma unroll
    for (int o = 128; o; o >>= 1) {
        if (t < o) s[t] += s[t + o];
        __syncthreads();
    }
    if (t == 0) part[blockIdx.x] = s[0];
}

__global__ __launch_bounds__(512) void scan2_kernel(int* part, int nb)
{
    __shared__ int s[512];
    int t = threadIdx.x;
    int v = (t < nb) ? part[t] : 0;
    s[t] = v;
    __syncthreads();
#pragma unroll
    for (int o = 1; o < 512; o <<= 1) {
        int add = (t >= o) ? s[t - o] : 0;
        __syncthreads();
        s[t] += add;
        __syncthreads();
    }
    if (t < nb) part[t] = t ? s[t - 1] : 0;  // exclusive
}

__global__ __launch_bounds__(256) void scan3_kernel(
    const int* __restrict__ cnt, const int* __restrict__ part,
    int* __restrict__ off, int* __restrict__ cur, int n, int E)
{
    __shared__ int s[256];
    int t = threadIdx.x;
    int i = blockIdx.x * 256 + t;
    int v = (i < n) ? cnt[i] : 0;
    s[t] = v;
    __syncthreads();
#pragma unroll
    for (int o = 1; o < 256; o <<= 1) {
        int add = (t >= o) ? s[t - o] : 0;
        __syncthreads();
        s[t] += add;
        __syncthreads();
    }
    int excl = (t ? s[t - 1] : 0) + part[blockIdx.x];
    if (i < n) { off[i] = excl; cur[i] = excl; }
    if (i == 0) off[n] = E;
}

__global__ __launch_bounds__(256) void fill_kernel(
    const int* __restrict__ src, const int* __restrict__ dst,
    int* __restrict__ cur, int* __restrict__ srcp, int E)
{
    int i = blockIdx.x * blockDim.x + threadIdx.x;
    if (i >= E) return;
    int pos = atomicAdd(&cur[dst[i]], 1);
    srcp[pos] = src[i];
}

// ================= fused GAT aggregate =================
// One warp per destination node. Handles BOTH incoming edge types, adds Wh_self,
// applies ReLU, writes the output row once (no atomics, no memset needed).
__device__ __forceinline__ void gat_accum(
    const int* __restrict__ off, const int* __restrict__ srcp,
    const float* __restrict__ ssrc, float sd,
    const float* __restrict__ Whm, int d, int lane, float4& acc)
{
    int beg = off[d], end = off[d + 1];
    if (beg == end) return;

    // pass 1: denom (lane-strided, warp reduce)
    float den = 0.f;
    for (int i = beg + lane; i < end; i += 32) {
        float e = ssrc[srcp[i]] + sd;
        e = e > 0.f ? e : SLOPE * e;
        den += __expf(e);
    }
#pragma unroll
    for (int o = 16; o; o >>= 1) den += __shfl_xor_sync(0xffffffffu, den, o);
    float inv = 1.0f / den;

    // pass 2: weighted gather-accumulate, 2-edge unrolled for MLP
    int i = beg;
    for (; i + 1 < end; i += 2) {
        int s0 = srcp[i], s1 = srcp[i + 1];
        float e0 = ssrc[s0] + sd; e0 = e0 > 0.f ? e0 : SLOPE * e0;
        float e1 = ssrc[s1] + sd; e1 = e1 > 0.f ? e1 : SLOPE * e1;
        float w0 = __expf(e0) * inv;
        float w1 = __expf(e1) * inv;
        float4 v0 = *(const float4*)(Whm + (size_t)s0 * DOUT + lane * 4);
        float4 v1 = *(const float4*)(Whm + (size_t)s1 * DOUT + lane * 4);
        acc.x += w0 * v0.x + w1 * v1.x;
        acc.y += w0 * v0.y + w1 * v1.y;
        acc.z += w0 * v0.z + w1 * v1.z;
        acc.w += w0 * v0.w + w1 * v1.w;
    }
    if (i < end) {
        int s0 = srcp[i];
        float e0 = ssrc[s0] + sd; e0 = e0 > 0.f ? e0 : SLOPE * e0;
        float w0 = __expf(e0) * inv;
        float4 v0 = *(const float4*)(Whm + (size_t)s0 * DOUT + lane * 4);
        acc.x += w0 * v0.x; acc.y += w0 * v0.y;
        acc.z += w0 * v0.z; acc.w += w0 * v0.w;
    }
}

__global__ __launch_bounds__(256) void gat_aggregate_kernel(
    const int* __restrict__ off1, const int* __restrict__ srcp1,
    const float* __restrict__ ssrc1, const float* __restrict__ sdst1,
    const float* __restrict__ Whm1,
    const int* __restrict__ off2, const int* __restrict__ srcp2,
    const float* __restrict__ ssrc2, const float* __restrict__ sdst2,
    const float* __restrict__ Whm2,
    const float* __restrict__ Whself, float* __restrict__ out, int n)
{
    int d    = (blockIdx.x * blockDim.x + threadIdx.x) >> 5;
    int lane = threadIdx.x & 31;
    if (d >= n) return;

    float4 acc = make_float4(0.f, 0.f, 0.f, 0.f);
    gat_accum(off1, srcp1, ssrc1, sdst1[d], Whm1, d, lane, acc);
    gat_accum(off2, srcp2, ssrc2, sdst2[d], Whm2, d, lane, acc);

    float4 self = *(const float4*)(Whself + (size_t)d * DOUT + lane * 4);
    float4 r;
    r.x = fmaxf(self.x + acc.x, 0.f);
    r.y = fmaxf(self.y + acc.y, 0.f);
    r.z = fmaxf(self.z + acc.z, 0.f);
    r.w = fmaxf(self.w + acc.w, 0.f);
    *(float4*)(out + (size_t)d * DOUT + lane * 4) = r;
}

// ---------------- host launcher ----------------
extern "C" void kernel_launch(void* const* d_in, const int* in_sizes, int n_in,
                              void* d_out, int out_size)
{
    (void)n_in; (void)out_size;
    const float* feat_P = (const float*)d_in[0];
    const float* feat_A = (const float*)d_in[1];
    const int* e_src[4] = { (const int*)d_in[2], (const int*)d_in[4],
                            (const int*)d_in[6], (const int*)d_in[8] };  // p2p,p2a,a2p,a2a
    const int* e_dst[4] = { (const int*)d_in[3], (const int*)d_in[5],
                            (const int*)d_in[7], (const int*)d_in[9] };
    const int  e_cnt[4] = { in_sizes[2], in_sizes[4], in_sizes[6], in_sizes[8] };

    const float* W_P   = (const float*)d_in[10]; const float* b_P   = (const float*)d_in[11];
    const float* W_A   = (const float*)d_in[12]; const float* b_A   = (const float*)d_in[13];
    const float* W_p2p = (const float*)d_in[14]; const float* b_p2p = (const float*)d_in[15];
    const float* W_p2a = (const float*)d_in[16]; const float* b_p2a = (const float*)d_in[17];
    const float* W_a2p = (const float*)d_in[18]; const float* b_a2p = (const float*)d_in[19];
    const float* W_a2a = (const float*)d_in[20]; const float* b_a2a = (const float*)d_in[21];
    const float* a_p2p = (const float*)d_in[22];
    const float* a_p2a = (const float*)d_in[23];
    const float* a_a2p = (const float*)d_in[24];
    const float* a_a2a = (const float*)d_in[25];

    const int n_p = in_sizes[0] / DIN;
    const int n_a = in_sizes[1] / DIN;

    float *whb, *ssrcb, *sdstb;
    int *cntb, *curb, *offb, *partb, *srcpb;
    cudaGetSymbolAddress((void**)&whb,   g_Wh);
    cudaGetSymbolAddress((void**)&ssrcb, g_ssrc);
    cudaGetSymbolAddress((void**)&sdstb, g_sdst);
    cudaGetSymbolAddress((void**)&cntb,  g_cnt);
    cudaGetSymbolAddress((void**)&curb,  g_cur);
    cudaGetSymbolAddress((void**)&offb,  g_off);
    cudaGetSymbolAddress((void**)&partb, g_part);
    cudaGetSymbolAddress((void**)&srcpb, g_srcp);

    float* Wh[6];
    for (int i = 0; i < 6; i++) Wh[i] = whb + (size_t)i * NP_MAX * DOUT;

    float* outP = (float*)d_out;
    float* outA = outP + (size_t)n_p * DOUT;

    // ---- CSR build for all 4 edge types (independent of GEMMs) ----
    cudaMemsetAsync(cntb, 0, 4 * (size_t)NP_MAX * sizeof(int));
    const int n_dst_t[4] = { n_p, n_a, n_p, n_a };
    for (int t = 0; t < 4; t++) {
        int E = e_cnt[t];
        int n = n_dst_t[t];
        int NB = (n + 255) / 256;
        int* cnt_t  = cntb  + (size_t)t * NP_MAX;
        int* cur_t  = curb  + (size_t)t * NP_MAX;
        int* off_t  = offb  + (size_t)t * (NP_MAX + 1);
        int* part_t = partb + (size_t)t * 512;
        int* srcp_t = srcpb + (size_t)t * E_MAX;
        hist_kernel<<<(E + 255) / 256, 256>>>(e_dst[t], cnt_t, E);
        scan1_kernel<<<NB, 256>>>(cnt_t, part_t, n);
        scan2_kernel<<<1, 512>>>(part_t, NB);
        scan3_kernel<<<NB, 256>>>(cnt_t, part_t, off_t, cur_t, n, E);
        fill_kernel<<<(E + 255) / 256, 256>>>(e_src[t], e_dst[t], cur_t, srcp_t, E);
    }

    // ---- tensor-core GEMMs: one launch per node type, 3 weight groups each ----
    cudaFuncSetAttribute(gemm_tc_kernel, cudaFuncAttributeMaxDynamicSharedMemorySize, SMEM_DYN);

    GemmArgs gp;
    gp.A = feat_P; gp.M = n_p;
    gp.W[0] = W_P;   gp.bias[0] = b_P;   gp.C[0] = Wh[0];
    gp.W[1] = W_p2p; gp.bias[1] = b_p2p; gp.C[1] = Wh[2];
    gp.W[2] = W_p2a; gp.bias[2] = b_p2a; gp.C[2] = Wh[3];
    gp.av0[0] = a_p2p + DOUT; gp.s0[0] = sdstb + 0 * NP_MAX;
    gp.av1[0] = a_a2p + DOUT; gp.s1[0] = sdstb + 2 * NP_MAX;
    gp.av0[1] = a_p2p;        gp.s0[1] = ssrcb + 0 * NP_MAX;
    gp.av1[1] = nullptr;      gp.s1[1] = nullptr;
    gp.av0[2] = a_p2a;        gp.s0[2] = ssrcb + 1 * NP_MAX;
    gp.av1[2] = nullptr;      gp.s1[2] = nullptr;

    GemmArgs gaa;
    gaa.A = feat_A; gaa.M = n_a;
    gaa.W[0] = W_A;   gaa.bias[0] = b_A;   gaa.C[0] = Wh[1];
    gaa.W[1] = W_a2p; gaa.bias[1] = b_a2p; gaa.C[1] = Wh[4];
    gaa.W[2] = W_a2a; gaa.bias[2] = b_a2a; gaa.C[2] = Wh[5];
    gaa.av0[0] = a_p2a + DOUT; gaa.s0[0] = sdstb + 1 * NP_MAX;
    gaa.av1[0] = a_a2a + DOUT; gaa.s1[0] = sdstb + 3 * NP_MAX;
    gaa.av0[1] = a_a2p;        gaa.s0[1] = ssrcb + 2 * NP_MAX;
    gaa.av1[1] = nullptr;      gaa.s1[1] = nullptr;
    gaa.av0[2] = a_a2a;        gaa.s0[2] = ssrcb + 3 * NP_MAX;
    gaa.av1[2] = nullptr;      gaa.s1[2] = nullptr;

    gemm_tc_kernel<<<dim3(3, (n_p + 127) / 128), 256, SMEM_DYN>>>(gp);
    gemm_tc_kernel<<<dim3(3, (n_a + 127) / 128), 256, SMEM_DYN>>>(gaa);

    // ---- fused aggregate + ReLU (one warp per dst node) ----
    // P receives p2p (t0) and a2p (t2); A receives p2a (t1) and a2a (t3).
    gat_aggregate_kernel<<<(n_p + 7) / 8, 256>>>(
        offb + 0 * (NP_MAX + 1), srcpb + (size_t)0 * E_MAX, ssrcb + 0 * NP_MAX, sdstb + 0 * NP_MAX, Wh[2],
        offb + 2 * (NP_MAX + 1), srcpb + (size_t)2 * E_MAX, ssrcb + 2 * NP_MAX, sdstb + 2 * NP_MAX, Wh[4],
        Wh[0], outP, n_p);
    gat_aggregate_kernel<<<(n_a + 7) / 8, 256>>>(
        offb + 1 * (NP_MAX + 1), srcpb + (size_t)1 * E_MAX, ssrcb + 1 * NP_MAX, sdstb + 1 * NP_MAX, Wh[3],
        offb + 3 * (NP_MAX + 1), srcpb + (size_t)3 * E_MAX, ssrcb + 3 * NP_MAX, sdstb + 3 * NP_MAX, Wh[5],
        Wh[1], outA, n_a);
}